// round 16
// baseline (speedup 1.0000x reference)
#include <cuda_runtime.h>

#define NT 128
#define NH 8
#define NL 3
#define LOG2E 1.4426950408889634f

#define O_WK  0
#define O_WQ  24
#define O_WV  48
#define O_WP  72
#define O_BP  96
#define O_W1  99
#define O_B1  111
#define O_W2  123
#define O_B2  135
#define O_WLM 138
#define O_BLM 139
#define NWTS  140

__device__ __forceinline__ float ex2(float x) {
    float y;
    asm("ex2.approx.ftz.f32 %0, %1;" : "=f"(y) : "f"(x));
    return y;
}

__device__ __forceinline__ float redux_max_nn(float x) {
    unsigned r;
    asm("redux.sync.max.u32 %0, %1, 0xffffffff;" : "=r"(r) : "r"(__float_as_uint(x)));
    return __uint_as_float(r);
}
__device__ __forceinline__ float redux_min_nn(float x) {
    unsigned r;
    asm("redux.sync.min.u32 %0, %1, 0xffffffff;" : "=r"(r) : "r"(__float_as_uint(x)));
    return __uint_as_float(r);
}

struct OS { float m, d, n; };
__device__ __forceinline__ OS comb(OS a, OS b) {
    float mx = fmaxf(a.m, b.m);
    float mn = fminf(a.m, b.m);
    float e  = ex2(mn - mx);
    bool  bl = a.m < b.m;
    float sa = bl ? e : 1.0f;
    float sb = bl ? 1.0f : e;
    OS r; r.m = mx; r.d = fmaf(a.d, sa, b.d * sb); r.n = fmaf(a.n, sa, b.n * sb);
    return r;
}

// exact online-softmax exclusive-prefix scan (fallback)
__device__ __forceinline__ void monoid_scan(
    float ch, float xx0, float xx1, float xx2, float xx3,
    float uu0, float uu1, float uu2, float uu3, int lid,
    float& h0, float& h1, float& h2, float& h3)
{
    OS a0 = { ch*uu0, 1.0f, xx0 };
    OS a1 = comb(a0, { ch*uu1, 1.0f, xx1 });
    OS a2 = comb(a1, { ch*uu2, 1.0f, xx2 });
    OS a3 = comb(a2, { ch*uu3, 1.0f, xx3 });
    OS agg = a3;
    #pragma unroll
    for (int o = 1; o < 32; o <<= 1) {
        OS up;
        up.m = __shfl_up_sync(0xffffffffu, agg.m, o);
        up.d = __shfl_up_sync(0xffffffffu, agg.d, o);
        up.n = __shfl_up_sync(0xffffffffu, agg.n, o);
        if (lid >= o) agg = comb(up, agg);
    }
    OS P;
    P.m = __shfl_up_sync(0xffffffffu, agg.m, 1);
    P.d = __shfl_up_sync(0xffffffffu, agg.d, 1);
    P.n = __shfl_up_sync(0xffffffffu, agg.n, 1);
    if (lid == 0) { P.m = -1e30f; P.d = 0.0f; P.n = 0.0f; }
    OS q1 = comb(P, a0);
    OS q2 = comb(P, a1);
    OS q3 = comb(P, a2);
    h0 = (lid == 0) ? 0.0f : __fdividef(P.n, P.d);
    h1 = __fdividef(q1.n, q1.d);
    h2 = __fdividef(q2.n, q2.d);
    h3 = __fdividef(q3.n, q3.d);
}

__global__ __launch_bounds__(256) void cat_kernel(
    const float* __restrict__ X,
    const float* __restrict__ wk, const float* __restrict__ wq, const float* __restrict__ wv,
    const float* __restrict__ Wp, const float* __restrict__ bp,
    const float* __restrict__ W1, const float* __restrict__ b1,
    const float* __restrict__ W2, const float* __restrict__ b2,
    const float* __restrict__ w_lm, const float* __restrict__ b_lm,
    float* __restrict__ out)
{
    __shared__ float W[NWTS];
    __shared__ float ps[NH][2][NT];  // [head][batch][pos] partial y
    __shared__ float xs[2][NT];      // [batch][pos] x between layers

    const int tid = threadIdx.x;
    const int wr  = tid >> 5;        // 0..7: head id
    const int lid = tid & 31;
    const int bA  = blockIdx.x * 2;
    const int bB  = bA + 1;

    float4 xvA = reinterpret_cast<const float4*>(X + bA * NT)[lid];
    float4 xvB = reinterpret_cast<const float4*>(X + bB * NT)[lid];

    if (tid < NWTS) {
        int i = tid;
        float v;
        if      (i < 24)  v = wk[i];
        else if (i < 48)  v = wq[i - 24];
        else if (i < 72)  v = wv[i - 48];
        else if (i < 96)  v = Wp[i - 72];
        else if (i < 99)  v = bp[i - 96];
        else if (i < 111) v = W1[i - 99];
        else if (i < 123) v = b1[i - 111];
        else if (i < 135) v = W2[i - 123];
        else if (i < 138) v = b2[i - 135];
        else if (i == 138) v = w_lm[0];
        else               v = b_lm[0];
        W[i] = v;
    }
    __syncthreads();

    // hoist this head's per-layer scan weights
    float c_r[NL], coef_r[NL], ca_r[NL];
    #pragma unroll
    for (int l = 0; l < NL; ++l) {
        float cc = W[O_WK + l*NH + wr] * W[O_WQ + l*NH + wr] * LOG2E;
        c_r[l]    = cc;
        ca_r[l]   = fabsf(cc);
        coef_r[l] = W[O_WV + l*NH + wr] * W[O_WP + l*NH + wr];
    }

    float xA0 = xvA.x, xA1 = xvA.y, xA2 = xvA.z, xA3 = xvA.w;
    float xB0 = xvB.x, xB1 = xvB.y, xB2 = xvB.z, xB3 = xvB.w;

    #pragma unroll
    for (int l = 0; l < NL; ++l) {
        const float uA0 = xA0*xA0, uA1 = xA1*xA1, uA2 = xA2*xA2, uA3 = xA3*xA3;
        const float uB0 = xB0*xB0, uB1 = xB1*xB1, uB2 = xB2*xB2, uB3 = xB3*xB3;

        const float umxA = redux_max_nn(fmaxf(fmaxf(uA0, uA1), fmaxf(uA2, uA3)));
        const float umnA = redux_min_nn(fminf(fminf(uA0, uA1), fminf(uA2, uA3)));
        const float umxB = redux_max_nn(fmaxf(fmaxf(uB0, uB1), fmaxf(uB2, uB3)));
        const float umnB = redux_min_nn(fminf(fminf(uB0, uB1), fminf(uB2, uB3)));

        const float ch = c_r[l];
        const float cf = coef_r[l];

        float pA0, pA1, pA2, pA3, pB0, pB1, pB2, pB3;

        if (ca_r[l] * fmaxf(umxA - umnA, umxB - umnB) < 120.0f) {
            // ---- two independent additive scans (A,B) interleaved ----
            const float KA = ((ch > 0.0f) ? ch * umxA : ch * umnA) - 63.0f;
            const float KB = ((ch > 0.0f) ? ch * umxB : ch * umnB) - 63.0f;
            float eA0 = ex2(fmaf(ch, uA0, -KA));
            float eB0 = ex2(fmaf(ch, uB0, -KB));
            float eA1 = ex2(fmaf(ch, uA1, -KA));
            float eB1 = ex2(fmaf(ch, uB1, -KB));
            float eA2 = ex2(fmaf(ch, uA2, -KA));
            float eB2 = ex2(fmaf(ch, uB2, -KB));
            float eA3 = ex2(fmaf(ch, uA3, -KA));
            float eB3 = ex2(fmaf(ch, uB3, -KB));
            float nA0 = eA0*xA0, nA1 = eA1*xA1, nA2 = eA2*xA2, nA3 = eA3*xA3;
            float nB0 = eB0*xB0, nB1 = eB1*xB1, nB2 = eB2*xB2, nB3 = eB3*xB3;

            float dA01 = eA0 + eA1, mA01 = nA0 + nA1;
            float dB01 = eB0 + eB1, mB01 = nB0 + nB1;
            float dA012 = dA01 + eA2, mA012 = mA01 + nA2;
            float dB012 = dB01 + eB2, mB012 = mB01 + nB2;
            float dAT = dA012 + eA3, mAT = mA012 + nA3;
            float dBT = dB012 + eB3, mBT = mB012 + nB3;

            float sdA = dAT, snA = mAT, sdB = dBT, snB = mBT;
            #pragma unroll
            for (int o = 1; o < 32; o <<= 1) {
                float a = __shfl_up_sync(0xffffffffu, sdA, o);
                float b = __shfl_up_sync(0xffffffffu, snA, o);
                float c = __shfl_up_sync(0xffffffffu, sdB, o);
                float d = __shfl_up_sync(0xffffffffu, snB, o);
                if (lid >= o) { sdA += a; snA += b; sdB += c; snB += d; }
            }
            float PdA = sdA - dAT, PnA = snA - mAT;
            float PdB = sdB - dBT, PnB = snB - mBT;

            float hA0 = __fdividef(PnA, PdA + 1e-37f);
            float hB0 = __fdividef(PnB, PdB + 1e-37f);
            float hA1 = __fdividef(PnA + nA0,   PdA + eA0);
            float hB1 = __fdividef(PnB + nB0,   PdB + eB0);
            float hA2 = __fdividef(PnA + mA01,  PdA + dA01);
            float hB2 = __fdividef(PnB + mB01,  PdB + dB01);
            float hA3 = __fdividef(PnA + mA012, PdA + dA012);
            float hB3 = __fdividef(PnB + mB012, PdB + dB012);
            pA0 = hA0 * cf; pA1 = hA1 * cf; pA2 = hA2 * cf; pA3 = hA3 * cf;
            pB0 = hB0 * cf; pB1 = hB1 * cf; pB2 = hB2 * cf; pB3 = hB3 * cf;
        } else {
            float h0, h1, h2, h3;
            monoid_scan(ch, xA0, xA1, xA2, xA3, uA0, uA1, uA2, uA3, lid, h0, h1, h2, h3);
            pA0 = h0 * cf; pA1 = h1 * cf; pA2 = h2 * cf; pA3 = h3 * cf;
            monoid_scan(ch, xB0, xB1, xB2, xB3, uB0, uB1, uB2, uB3, lid, h0, h1, h2, h3);
            pB0 = h0 * cf; pB1 = h1 * cf; pB2 = h2 * cf; pB3 = h3 * cf;
        }

        // ---- position-split epilogue, both batches, all 256 threads ----
        reinterpret_cast<float4*>(ps[wr][0])[lid] = make_float4(pA0, pA1, pA2, pA3);
        reinterpret_cast<float4*>(ps[wr][1])[lid] = make_float4(pB0, pB1, pB2, pB3);
        __syncthreads();

        {
            const int eb = tid >> 7;        // 0: batch A, 1: batch B
            const int p  = tid & 127;
            float y = W[O_BP + l];
            #pragma unroll
            for (int w = 0; w < NH; ++w) y += ps[w][eb][p];

            float f = W[O_B2 + l];
            #pragma unroll
            for (int k = 0; k < 4; ++k)
                f = fmaf(fmaxf(fmaf(y, W[O_W1 + l*4 + k], W[O_B1 + l*4 + k]), 0.0f),
                         W[O_W2 + l*4 + k], f);
            float xn = y + f;

            if (l == NL - 1) {
                out[(bA + eb) * NT + p] = fmaf(xn, W[O_WLM], W[O_BLM]);
            } else {
                xs[eb][p] = xn;
            }
        }

        if (l < NL - 1) {
            __syncthreads();
            float4 xnA = reinterpret_cast<const float4*>(xs[0])[lid];
            float4 xnB = reinterpret_cast<const float4*>(xs[1])[lid];
            xA0 = xnA.x; xA1 = xnA.y; xA2 = xnA.z; xA3 = xnA.w;
            xB0 = xnB.x; xB1 = xnB.y; xB2 = xnB.z; xB3 = xnB.w;
        }
    }
}

extern "C" void kernel_launch(void* const* d_in, const int* in_sizes, int n_in,
                              void* d_out, int out_size) {
    (void)in_sizes; (void)n_in; (void)out_size;
    cat_kernel<<<256, 256>>>(
        (const float*)d_in[0],  // X
        (const float*)d_in[1],  // wk
        (const float*)d_in[2],  // wq
        (const float*)d_in[3],  // wv
        (const float*)d_in[4],  // Wp
        (const float*)d_in[5],  // bp
        (const float*)d_in[6],  // W1
        (const float*)d_in[7],  // b1
        (const float*)d_in[8],  // W2
        (const float*)d_in[9],  // b2
        (const float*)d_in[10], // w_lm
        (const float*)d_in[11], // b_lm
        (float*)d_out);
}